// round 15
// baseline (speedup 1.0000x reference)
#include <cuda_runtime.h>
#include <cuda_fp16.h>
#include <math_constants.h>
#include <cstdint>
#include <cstring>

// Problem constants
#define PB 2
#define PS 2048
#define PE 1024
#define PH 16
#define PHD 64
#define PBH (PB * PH)        // 32
#define PM (PB * PS)         // 4096

// ---------------------------------------------------------------------------
// helpers (sm_100-safe: mma.sync only)
// ---------------------------------------------------------------------------
__device__ __forceinline__ uint32_t h2pack(float x, float y) {
    __half2 h = __floats2half2_rn(x, y);
    uint32_t u;
    memcpy(&u, &h, 4);
    return u;
}
__device__ __forceinline__ void mma_f16(float c[4], const uint32_t a[4], const uint32_t b[2]) {
    asm("mma.sync.aligned.m16n8k16.row.col.f32.f16.f16.f32 "
        "{%0,%1,%2,%3}, {%4,%5,%6,%7}, {%8,%9}, {%0,%1,%2,%3};"
        : "+f"(c[0]), "+f"(c[1]), "+f"(c[2]), "+f"(c[3])
        : "r"(a[0]), "r"(a[1]), "r"(a[2]), "r"(a[3]), "r"(b[0]), "r"(b[1]));
}

// ---------------------------------------------------------------------------
// Scratch (no cudaMalloc allowed)
// ---------------------------------------------------------------------------
__device__ float g_qp[PM * PE];
__device__ float g_kp[PM * PE];
__device__ float g_vp[PM * PE];
__device__ float g_ao[PM * PE];

// ---------------------------------------------------------------------------
// FP16 GEMM: C[M,N] = A[M,K] @ B[N,K]^T  (torch Linear; fp32 accumulate)
// CTA 128x128, 8 warps (2x4), warp tile 64x32, K-tile 32 (2 x k16 mma steps).
// Double-buffered smem (one sync per K-tile), LDG register prefetch,
// fp32->fp16 cvt at staging. Row pitch 40 halves (20 words):
//   fragment word bank = (20*gr + 8*s + cc) mod 32;
//   {0,20,8,28,16,4,24,12} + {0..3} covers all 32 banks -> conflict-free.
// ---------------------------------------------------------------------------
#define GP16 40                        // halves per row
#define GBUF (128 * GP16)              // halves per matrix per buffer

__global__ __launch_bounds__(256, 2)
void gemm_f16(const float* __restrict__ A0, const float* __restrict__ B0, float* __restrict__ C0,
              const float* __restrict__ A1, const float* __restrict__ B1, float* __restrict__ C1,
              const float* __restrict__ A2, const float* __restrict__ B2, float* __restrict__ C2,
              int M, int N, int K)
{
    __shared__ __half Sm[2][2 * GBUF];   // [buf][ A | B ]  (40960 B total)

    const float* A = A0; const float* B = B0; float* C = C0;
    if (blockIdx.z == 1) { A = A1; B = B1; C = C1; }
    else if (blockIdx.z == 2) { A = A2; B = B2; C = C2; }

    const int tid  = threadIdx.x;
    const int lane = tid & 31;
    const int warp = tid >> 5;
    const int wm   = warp >> 2;          // 0..1
    const int wn   = warp & 3;           // 0..3
    const int gr   = lane >> 2;          // 0..7
    const int cc   = lane & 3;           // 0..3

    const int bm = blockIdx.y * 128;
    const int bn = blockIdx.x * 128;

    const int lr = tid >> 1;             // 0..127
    const int lq = (tid & 1) * 16;       // 0 or 16

    const float* Ap = A + (size_t)(bm + lr) * K + lq;
    const float* Bp = B + (size_t)(bn + lr) * K + lq;

    float acc[4][4][4];
#pragma unroll
    for (int mt = 0; mt < 4; mt++)
#pragma unroll
        for (int nt = 0; nt < 4; nt++)
#pragma unroll
            for (int r = 0; r < 4; r++) acc[mt][nt][r] = 0.f;

    float4 pa[4], pb[4];
#pragma unroll
    for (int i = 0; i < 4; i++) {
        pa[i] = *(const float4*)(Ap + i * 4);
        pb[i] = *(const float4*)(Bp + i * 4);
    }

    auto stage = [&](int buf) {
        __half* Ad = &Sm[buf][lr * GP16 + lq];
        __half* Bd = Ad + GBUF;
        *(uint4*)(Ad)     = make_uint4(h2pack(pa[0].x, pa[0].y), h2pack(pa[0].z, pa[0].w),
                                       h2pack(pa[1].x, pa[1].y), h2pack(pa[1].z, pa[1].w));
        *(uint4*)(Ad + 8) = make_uint4(h2pack(pa[2].x, pa[2].y), h2pack(pa[2].z, pa[2].w),
                                       h2pack(pa[3].x, pa[3].y), h2pack(pa[3].z, pa[3].w));
        *(uint4*)(Bd)     = make_uint4(h2pack(pb[0].x, pb[0].y), h2pack(pb[0].z, pb[0].w),
                                       h2pack(pb[1].x, pb[1].y), h2pack(pb[1].z, pb[1].w));
        *(uint4*)(Bd + 8) = make_uint4(h2pack(pb[2].x, pb[2].y), h2pack(pb[2].z, pb[2].w),
                                       h2pack(pb[3].x, pb[3].y), h2pack(pb[3].z, pb[3].w));
    };

    stage(0);
    __syncthreads();

    const int NT = K / 32;   // 32
    int buf = 0;
    for (int t = 0; t < NT; t++) {
        const bool more = (t + 1 < NT);
        if (more) {
            const int ko = (t + 1) * 32;
#pragma unroll
            for (int i = 0; i < 4; i++) {
                pa[i] = *(const float4*)(Ap + ko + i * 4);
                pb[i] = *(const float4*)(Bp + ko + i * 4);
            }
        }

        const __half* As = &Sm[buf][0];
        const __half* Bs = As + GBUF;
#pragma unroll
        for (int s = 0; s < 2; s++) {          // 2 x k16 steps
            const int kh = s * 16 + 2 * cc;
            uint32_t afr[4][4], bfr[4][2];
#pragma unroll
            for (int mt = 0; mt < 4; mt++) {
                const int r0 = wm * 64 + mt * 16 + gr;
                memcpy(&afr[mt][0], &As[r0 * GP16 + kh], 4);
                memcpy(&afr[mt][1], &As[(r0 + 8) * GP16 + kh], 4);
                memcpy(&afr[mt][2], &As[r0 * GP16 + kh + 8], 4);
                memcpy(&afr[mt][3], &As[(r0 + 8) * GP16 + kh + 8], 4);
            }
#pragma unroll
            for (int nt = 0; nt < 4; nt++) {
                const int nr = wn * 32 + nt * 8 + gr;
                memcpy(&bfr[nt][0], &Bs[nr * GP16 + kh], 4);
                memcpy(&bfr[nt][1], &Bs[nr * GP16 + kh + 8], 4);
            }
#pragma unroll
            for (int mt = 0; mt < 4; mt++)
#pragma unroll
                for (int nt = 0; nt < 4; nt++)
                    mma_f16(acc[mt][nt], afr[mt], bfr[nt]);
        }

        if (more) {
            stage(buf ^ 1);
            __syncthreads();
            buf ^= 1;
        }
    }

    // epilogue (fp32)
#pragma unroll
    for (int mt = 0; mt < 4; mt++) {
        const int r0 = bm + wm * 64 + mt * 16 + gr;
#pragma unroll
        for (int nt = 0; nt < 4; nt++) {
            const int cb = bn + wn * 32 + nt * 8 + 2 * cc;
            *(float2*)(C + (size_t)r0 * N + cb)       = make_float2(acc[mt][nt][0], acc[mt][nt][1]);
            *(float2*)(C + (size_t)(r0 + 8) * N + cb) = make_float2(acc[mt][nt][2], acc[mt][nt][3]);
        }
    }
}

// ---------------------------------------------------------------------------
// Flash attention, fp16 mma.sync (EXACT R14 version — proven, ~150us)
//   Ks[64][72 halves], Vp[32][72 half2] (seq-pairs), Ps[128][72 halves]
// ---------------------------------------------------------------------------
#define KS16 72
#define PS16 72
#define VP2  72

__global__ __launch_bounds__(256, 2)
void flash_f16(const float* __restrict__ Q, const float* __restrict__ K,
               const float* __restrict__ V, float* __restrict__ O,
               const int* __restrict__ maskflag)
{
    __shared__ __half  Ks[64 * KS16];
    __shared__ __half2 Vp[32 * VP2];
    __shared__ __half  Ps[128 * PS16];

    const int tid  = threadIdx.x;
    const int lane = tid & 31;
    const int warp = tid >> 5;
    const int gr   = lane >> 2;
    const int cc   = lane & 3;
    const int bh   = blockIdx.y;
    const int bx   = blockIdx.x;
    const int m0   = bx * 128;
    const int wr0  = warp * 16;

    const float* Qb = Q + (size_t)bh * PS * PHD;
    const float* Kb = K + (size_t)bh * PS * PHD;
    const float* Vb = V + (size_t)bh * PS * PHD;
    float*       Ob = O + (size_t)bh * PS * PHD + (size_t)m0 * PHD;

    for (int t = tid; t < 1024; t += 256) {
        int r = t >> 3, c8 = (t & 7) << 3;
        const float* src = Qb + (size_t)(m0 + r) * PHD + c8;
        float4 x0 = *(const float4*)(src);
        float4 x1 = *(const float4*)(src + 4);
        *(uint4*)&Ps[r * PS16 + c8] = make_uint4(
            h2pack(x0.x * 0.125f, x0.y * 0.125f), h2pack(x0.z * 0.125f, x0.w * 0.125f),
            h2pack(x1.x * 0.125f, x1.y * 0.125f), h2pack(x1.z * 0.125f, x1.w * 0.125f));
    }
    __syncthreads();

    uint32_t qa[4][4];
#pragma unroll
    for (int s = 0; s < 4; s++) {
        const int kh = s * 16 + 2 * cc;
        memcpy(&qa[s][0], &Ps[(wr0 + gr) * PS16 + kh], 4);
        memcpy(&qa[s][1], &Ps[(wr0 + gr + 8) * PS16 + kh], 4);
        memcpy(&qa[s][2], &Ps[(wr0 + gr) * PS16 + kh + 8], 4);
        memcpy(&qa[s][3], &Ps[(wr0 + gr + 8) * PS16 + kh + 8], 4);
    }
    __syncwarp();

    const bool causal = (*maskflag != 0);
    const int ntiles = causal ? (2 * bx + 2) : (PS / 64);

    float mr0 = -1e30f, mr1 = -1e30f, lr0 = 0.f, lr1 = 0.f;
    float o[8][4];
#pragma unroll
    for (int nt = 0; nt < 8; nt++)
#pragma unroll
        for (int r = 0; r < 4; r++) o[nt][r] = 0.f;

    for (int kt = 0; kt < ntiles; kt++) {
        const int n0 = kt * 64;

        for (int t = tid; t < 512; t += 256) {
            int r = t >> 3, c8 = (t & 7) << 3;
            const float* src = Kb + (size_t)(n0 + r) * PHD + c8;
            float4 x0 = *(const float4*)(src);
            float4 x1 = *(const float4*)(src + 4);
            *(uint4*)&Ks[r * KS16 + c8] = make_uint4(
                h2pack(x0.x, x0.y), h2pack(x0.z, x0.w),
                h2pack(x1.x, x1.y), h2pack(x1.z, x1.w));
        }
        for (int t = tid; t < 512; t += 256) {
            int p = t >> 4, c4 = (t & 15) << 2;
            const float* s0 = Vb + (size_t)(n0 + 2 * p) * PHD + c4;
            const float* s1 = s0 + PHD;
            float4 x0 = *(const float4*)s0;
            float4 x1 = *(const float4*)s1;
            *(uint4*)&Vp[p * VP2 + c4] = make_uint4(
                h2pack(x0.x, x1.x), h2pack(x0.y, x1.y),
                h2pack(x0.z, x1.z), h2pack(x0.w, x1.w));
        }
        __syncthreads();

        float s[8][4];
#pragma unroll
        for (int nt = 0; nt < 8; nt++)
#pragma unroll
            for (int r = 0; r < 4; r++) s[nt][r] = 0.f;

#pragma unroll
        for (int ks = 0; ks < 4; ks++) {
            const int kh = ks * 16 + 2 * cc;
#pragma unroll
            for (int nt = 0; nt < 8; nt++) {
                uint32_t b[2];
                memcpy(&b[0], &Ks[(nt * 8 + gr) * KS16 + kh], 4);
                memcpy(&b[1], &Ks[(nt * 8 + gr) * KS16 + kh + 8], 4);
                mma_f16(s[nt], qa[ks], b);
            }
        }

        const int rlo = m0 + wr0 + gr;
        const int rhi = rlo + 8;
        if (causal && (n0 + 63 > rlo)) {
#pragma unroll
            for (int nt = 0; nt < 8; nt++) {
                const int c0 = n0 + nt * 8 + 2 * cc;
                if (c0 > rlo)     s[nt][0] = -1e30f;
                if (c0 + 1 > rlo) s[nt][1] = -1e30f;
                if (c0 > rhi)     s[nt][2] = -1e30f;
                if (c0 + 1 > rhi) s[nt][3] = -1e30f;
            }
        }

        float tl = -1e30f, th = -1e30f;
#pragma unroll
        for (int nt = 0; nt < 8; nt++) {
            tl = fmaxf(tl, fmaxf(s[nt][0], s[nt][1]));
            th = fmaxf(th, fmaxf(s[nt][2], s[nt][3]));
        }
        tl = fmaxf(tl, __shfl_xor_sync(0xffffffffu, tl, 1));
        tl = fmaxf(tl, __shfl_xor_sync(0xffffffffu, tl, 2));
        th = fmaxf(th, __shfl_xor_sync(0xffffffffu, th, 1));
        th = fmaxf(th, __shfl_xor_sync(0xffffffffu, th, 2));

        const float mn0 = fmaxf(mr0, tl);
        const float mn1 = fmaxf(mr1, th);
        const float al0 = __expf(mr0 - mn0);
        const float al1 = __expf(mr1 - mn1);

        float sl = 0.f, sh = 0.f;
#pragma unroll
        for (int nt = 0; nt < 8; nt++) {
            float p0 = __expf(s[nt][0] - mn0);
            float p1 = __expf(s[nt][1] - mn0);
            float p2 = __expf(s[nt][2] - mn1);
            float p3 = __expf(s[nt][3] - mn1);
            sl += p0 + p1; sh += p2 + p3;
            uint32_t w0 = h2pack(p0, p1);
            uint32_t w1 = h2pack(p2, p3);
            memcpy(&Ps[(wr0 + gr) * PS16 + nt * 8 + 2 * cc], &w0, 4);
            memcpy(&Ps[(wr0 + gr + 8) * PS16 + nt * 8 + 2 * cc], &w1, 4);
        }
        sl += __shfl_xor_sync(0xffffffffu, sl, 1);
        sl += __shfl_xor_sync(0xffffffffu, sl, 2);
        sh += __shfl_xor_sync(0xffffffffu, sh, 1);
        sh += __shfl_xor_sync(0xffffffffu, sh, 2);

        lr0 = lr0 * al0 + sl;
        lr1 = lr1 * al1 + sh;
        mr0 = mn0; mr1 = mn1;

#pragma unroll
        for (int nt = 0; nt < 8; nt++) {
            o[nt][0] *= al0; o[nt][1] *= al0;
            o[nt][2] *= al1; o[nt][3] *= al1;
        }
        __syncwarp();

#pragma unroll
        for (int ks = 0; ks < 4; ks++) {
            const int kh = ks * 16 + 2 * cc;
            const int pp = ks * 8 + cc;
            uint32_t a[4];
            memcpy(&a[0], &Ps[(wr0 + gr) * PS16 + kh], 4);
            memcpy(&a[1], &Ps[(wr0 + gr + 8) * PS16 + kh], 4);
            memcpy(&a[2], &Ps[(wr0 + gr) * PS16 + kh + 8], 4);
            memcpy(&a[3], &Ps[(wr0 + gr + 8) * PS16 + kh + 8], 4);
#pragma unroll
            for (int nt = 0; nt < 8; nt++) {
                uint32_t b[2];
                memcpy(&b[0], &Vp[pp * VP2 + nt * 8 + gr], 4);
                memcpy(&b[1], &Vp[(pp + 4) * VP2 + nt * 8 + gr], 4);
                mma_f16(o[nt], a, b);
            }
        }
        __syncthreads();
    }

    const float i0 = 1.0f / lr0;
    const float i1 = 1.0f / lr1;
#pragma unroll
    for (int nt = 0; nt < 8; nt++) {
        const int cb = nt * 8 + 2 * cc;
        *(float2*)(Ob + (size_t)(wr0 + gr) * PHD + cb) =
            make_float2(o[nt][0] * i0, o[nt][1] * i0);
        *(float2*)(Ob + (size_t)(wr0 + gr + 8) * PHD + cb) =
            make_float2(o[nt][2] * i1, o[nt][3] * i1);
    }
}

// ---------------------------------------------------------------------------
// Launch
// ---------------------------------------------------------------------------
extern "C" void kernel_launch(void* const* d_in, const int* in_sizes, int n_in,
                              void* d_out, int out_size)
{
    const float* q  = (const float*)d_in[0];
    const float* k  = (const float*)d_in[1];
    const float* v  = (const float*)d_in[2];
    const float* wq = (const float*)d_in[3];
    const float* wk = (const float*)d_in[4];
    const float* wv = (const float*)d_in[5];
    const float* wo = (const float*)d_in[6];
    const int*   am = (const int*)d_in[7];
    float* out = (float*)d_out;

    float *qp, *kp, *vp, *ao;
    cudaGetSymbolAddress((void**)&qp, g_qp);
    cudaGetSymbolAddress((void**)&kp, g_kp);
    cudaGetSymbolAddress((void**)&vp, g_vp);
    cudaGetSymbolAddress((void**)&ao, g_ao);

    // fused Q/K/V projections (z = 0,1,2)
    dim3 gQKV(PE / 128, PM / 128, 3);   // (8, 32, 3)
    gemm_f16<<<gQKV, 256>>>(q, wq, qp,  k, wk, kp,  v, wv, vp, PM, PE, PE);

    dim3 gAttn(PS / 128, PBH);          // (16, 32)
    flash_f16<<<gAttn, 256>>>(qp, kp, vp, ao, am);

    // output projection
    dim3 gO(PE / 128, PM / 128, 1);
    gemm_f16<<<gO, 256>>>(ao, wo, out,  ao, wo, out,  ao, wo, out, PM, PE, PE);
}

// round 16
// speedup vs baseline: 1.1269x; 1.1269x over previous
#include <cuda_runtime.h>
#include <cuda_fp16.h>
#include <math_constants.h>
#include <cstdint>
#include <cstring>

// Problem constants
#define PB 2
#define PS 2048
#define PE 1024
#define PH 16
#define PHD 64
#define PBH (PB * PH)        // 32
#define PM (PB * PS)         // 4096

// ---------------------------------------------------------------------------
// helpers (sm_100-safe: mma.sync + cp.async only)
// ---------------------------------------------------------------------------
__device__ __forceinline__ uint32_t h2pack(float x, float y) {
    __half2 h = __floats2half2_rn(x, y);
    uint32_t u;
    memcpy(&u, &h, 4);
    return u;
}
__device__ __forceinline__ void mma_f16(float c[4], const uint32_t a[4], const uint32_t b[2]) {
    asm("mma.sync.aligned.m16n8k16.row.col.f32.f16.f16.f32 "
        "{%0,%1,%2,%3}, {%4,%5,%6,%7}, {%8,%9}, {%0,%1,%2,%3};"
        : "+f"(c[0]), "+f"(c[1]), "+f"(c[2]), "+f"(c[3])
        : "r"(a[0]), "r"(a[1]), "r"(a[2]), "r"(a[3]), "r"(b[0]), "r"(b[1]));
}
__device__ __forceinline__ uint32_t smem_u32(const void* p) {
    uint32_t a;
    asm("{ .reg .u64 t; cvta.to.shared.u64 t, %1; cvt.u32.u64 %0, t; }" : "=r"(a) : "l"(p));
    return a;
}
__device__ __forceinline__ void cp16(uint32_t s, const void* g) {
    asm volatile("cp.async.cg.shared.global [%0], [%1], 16;" :: "r"(s), "l"(g) : "memory");
}
#define CP_COMMIT() asm volatile("cp.async.commit_group;" ::: "memory")
#define CP_WAIT1()  asm volatile("cp.async.wait_group 1;" ::: "memory")
#define CP_WAIT0()  asm volatile("cp.async.wait_group 0;" ::: "memory")

// ---------------------------------------------------------------------------
// Scratch (no cudaMalloc allowed)
// ---------------------------------------------------------------------------
__device__ __half g_qh[PM * PE];      // fp16 copies of inputs
__device__ __half g_kh[PM * PE];
__device__ __half g_vh[PM * PE];
__device__ __half g_wqh[PE * PE];
__device__ __half g_wkh[PE * PE];
__device__ __half g_wvh[PE * PE];
__device__ __half g_woh[PE * PE];
__device__ __half g_qp[PM * PE];      // fp16 intermediates
__device__ __half g_kp[PM * PE];
__device__ __half g_vp[PM * PE];
__device__ __half g_ao[PM * PE];

// ---------------------------------------------------------------------------
// One-shot fp32 -> fp16 conversion (z selects array; grid-stride safe)
// ---------------------------------------------------------------------------
__global__ void cvt_f2h(const float* q, const float* k, const float* v,
                        const float* wq, const float* wk, const float* wv, const float* wo,
                        __half* qh, __half* kh, __half* vh,
                        __half* wqh, __half* wkh, __half* wvh, __half* woh)
{
    const int z = blockIdx.y;
    const float* s; __half* d; int n;
    switch (z) {
        case 0: s = q;  d = qh;  n = PM * PE; break;
        case 1: s = k;  d = kh;  n = PM * PE; break;
        case 2: s = v;  d = vh;  n = PM * PE; break;
        case 3: s = wq; d = wqh; n = PE * PE; break;
        case 4: s = wk; d = wkh; n = PE * PE; break;
        case 5: s = wv; d = wvh; n = PE * PE; break;
        default: s = wo; d = woh; n = PE * PE; break;
    }
    const int i = (blockIdx.x * 256 + threadIdx.x) * 8;
    if (i < n) {
        float4 a = *(const float4*)(s + i);
        float4 b = *(const float4*)(s + i + 4);
        *(uint4*)(d + i) = make_uint4(h2pack(a.x, a.y), h2pack(a.z, a.w),
                                      h2pack(b.x, b.y), h2pack(b.z, b.w));
    }
}

// ---------------------------------------------------------------------------
// FP16 GEMM (cp.async staging): C[M,N] = A[M,K] @ B[N,K]^T, fp32 accumulate.
// CTA 128x128, 8 warps (2x4), warp tile 64x32, K-tile 32 (2 x k16 steps).
// Staging = 4 x cp.async.cg 16B per thread per tile (no cvt, no RF round trip),
// 2-deep commit/wait pipeline. Fragment layout EXACT R15 (proven):
//   pitch 40 halves; word bank = (20*gr + 8*s + cc) mod 32 -> all 32 banks.
// outHalf: write __half (QKV / intermediates) else float (final output).
// ---------------------------------------------------------------------------
#define GP16 40
#define GBUF (128 * GP16)

__global__ __launch_bounds__(256, 2)
void gemm_h(const __half* __restrict__ A0, const __half* __restrict__ B0, void* C0,
            const __half* __restrict__ A1, const __half* __restrict__ B1, void* C1,
            const __half* __restrict__ A2, const __half* __restrict__ B2, void* C2,
            int outHalf, int M, int N, int K)
{
    __shared__ __half Sm[2][2 * GBUF];   // 40960 B

    const __half* A = A0; const __half* B = B0; void* Cv = C0;
    if (blockIdx.z == 1) { A = A1; B = B1; Cv = C1; }
    else if (blockIdx.z == 2) { A = A2; B = B2; Cv = C2; }

    const int tid  = threadIdx.x;
    const int lane = tid & 31;
    const int warp = tid >> 5;
    const int wm   = warp >> 2;
    const int wn   = warp & 3;
    const int gr   = lane >> 2;
    const int cc   = lane & 3;

    const int bm = blockIdx.y * 128;
    const int bn = blockIdx.x * 128;

    const int lr = tid >> 1;
    const int lq = (tid & 1) * 16;       // halves

    const __half* Agp = A + (size_t)(bm + lr) * K + lq;
    const __half* Bgp = B + (size_t)(bn + lr) * K + lq;
    const uint32_t sbase = smem_u32(Sm);
    const uint32_t aoff = (uint32_t)(lr * GP16 + lq) * 2;   // bytes within buffer

    float acc[4][4][4];
#pragma unroll
    for (int mt = 0; mt < 4; mt++)
#pragma unroll
        for (int nt = 0; nt < 4; nt++)
#pragma unroll
            for (int r = 0; r < 4; r++) acc[mt][nt][r] = 0.f;

    auto stage = [&](int buf, int ko) {
        const uint32_t ad = sbase + (uint32_t)buf * (4 * GBUF) + aoff;
        const uint32_t bd = ad + 2 * GBUF;
        cp16(ad,      Agp + ko);
        cp16(ad + 16, Agp + ko + 8);
        cp16(bd,      Bgp + ko);
        cp16(bd + 16, Bgp + ko + 8);
        CP_COMMIT();
    };

    const int NT = K / 32;   // 32
    stage(0, 0);
    stage(1, 32);

    for (int t = 0; t < NT; t++) {
        if (t == NT - 1) { CP_WAIT0(); } else { CP_WAIT1(); }
        __syncthreads();

        const int buf = t & 1;
        const __half* As = &Sm[buf][0];
        const __half* Bs = As + GBUF;
#pragma unroll
        for (int s = 0; s < 2; s++) {
            const int kh = s * 16 + 2 * cc;
            uint32_t afr[4][4], bfr[4][2];
#pragma unroll
            for (int mt = 0; mt < 4; mt++) {
                const int r0 = wm * 64 + mt * 16 + gr;
                memcpy(&afr[mt][0], &As[r0 * GP16 + kh], 4);
                memcpy(&afr[mt][1], &As[(r0 + 8) * GP16 + kh], 4);
                memcpy(&afr[mt][2], &As[r0 * GP16 + kh + 8], 4);
                memcpy(&afr[mt][3], &As[(r0 + 8) * GP16 + kh + 8], 4);
            }
#pragma unroll
            for (int nt = 0; nt < 4; nt++) {
                const int nr = wn * 32 + nt * 8 + gr;
                memcpy(&bfr[nt][0], &Bs[nr * GP16 + kh], 4);
                memcpy(&bfr[nt][1], &Bs[nr * GP16 + kh + 8], 4);
            }
#pragma unroll
            for (int mt = 0; mt < 4; mt++)
#pragma unroll
                for (int nt = 0; nt < 4; nt++)
                    mma_f16(acc[mt][nt], afr[mt], bfr[nt]);
        }

        if (t + 2 < NT) {
            __syncthreads();              // all warps done reading buf before overwrite
            stage(buf, (t + 2) * 32);
        }
    }

    // epilogue
    if (outHalf) {
        __half* C = (__half*)Cv;
#pragma unroll
        for (int mt = 0; mt < 4; mt++) {
            const int r0 = bm + wm * 64 + mt * 16 + gr;
#pragma unroll
            for (int nt = 0; nt < 4; nt++) {
                const int cb = bn + wn * 32 + nt * 8 + 2 * cc;
                uint32_t w0 = h2pack(acc[mt][nt][0], acc[mt][nt][1]);
                uint32_t w1 = h2pack(acc[mt][nt][2], acc[mt][nt][3]);
                memcpy(C + (size_t)r0 * N + cb, &w0, 4);
                memcpy(C + (size_t)(r0 + 8) * N + cb, &w1, 4);
            }
        }
    } else {
        float* C = (float*)Cv;
#pragma unroll
        for (int mt = 0; mt < 4; mt++) {
            const int r0 = bm + wm * 64 + mt * 16 + gr;
#pragma unroll
            for (int nt = 0; nt < 4; nt++) {
                const int cb = bn + wn * 32 + nt * 8 + 2 * cc;
                *(float2*)(C + (size_t)r0 * N + cb)       = make_float2(acc[mt][nt][0], acc[mt][nt][1]);
                *(float2*)(C + (size_t)(r0 + 8) * N + cb) = make_float2(acc[mt][nt][2], acc[mt][nt][3]);
            }
        }
    }
}

// ---------------------------------------------------------------------------
// Flash attention, fp16 in / fp16 out (fp32 softmax & accum).
// Structure = proven R14; inputs now fp16 so staging is pure copies.
// Q no longer prescaled: scale 1/8 applied to fp32 logits (more accurate).
//   Ks[64][72 halves], Vp[32][72 half2] (seq-pairs), Ps[128][72 halves]
// ---------------------------------------------------------------------------
#define KS16 72
#define PS16 72
#define VP2  72

__global__ __launch_bounds__(256, 2)
void flash_h(const __half* __restrict__ Q, const __half* __restrict__ K,
             const __half* __restrict__ V, __half* __restrict__ O,
             const int* __restrict__ maskflag)
{
    __shared__ __half  Ks[64 * KS16];
    __shared__ __half2 Vp[32 * VP2];
    __shared__ __half  Ps[128 * PS16];

    const int tid  = threadIdx.x;
    const int lane = tid & 31;
    const int warp = tid >> 5;
    const int gr   = lane >> 2;
    const int cc   = lane & 3;
    const int bh   = blockIdx.y;
    const int bx   = blockIdx.x;
    const int m0   = bx * 128;
    const int wr0  = warp * 16;

    const __half* Qb = Q + (size_t)bh * PS * PHD;
    const __half* Kb = K + (size_t)bh * PS * PHD;
    const __half* Vb = V + (size_t)bh * PS * PHD;
    __half*       Ob = O + (size_t)bh * PS * PHD + (size_t)m0 * PHD;

    // stage Q (direct copy; 128 rows x 64 halves)
    for (int t = tid; t < 1024; t += 256) {
        int r = t >> 3, c8 = (t & 7) << 3;
        *(uint4*)&Ps[r * PS16 + c8] = *(const uint4*)(Qb + (size_t)(m0 + r) * PHD + c8);
    }
    __syncthreads();

    uint32_t qa[4][4];
#pragma unroll
    for (int s = 0; s < 4; s++) {
        const int kh = s * 16 + 2 * cc;
        memcpy(&qa[s][0], &Ps[(wr0 + gr) * PS16 + kh], 4);
        memcpy(&qa[s][1], &Ps[(wr0 + gr + 8) * PS16 + kh], 4);
        memcpy(&qa[s][2], &Ps[(wr0 + gr) * PS16 + kh + 8], 4);
        memcpy(&qa[s][3], &Ps[(wr0 + gr + 8) * PS16 + kh + 8], 4);
    }
    __syncwarp();

    const bool causal = (*maskflag != 0);
    const int ntiles = causal ? (2 * bx + 2) : (PS / 64);

    float mr0 = -1e30f, mr1 = -1e30f, lr0 = 0.f, lr1 = 0.f;
    float o[8][4];
#pragma unroll
    for (int nt = 0; nt < 8; nt++)
#pragma unroll
        for (int r = 0; r < 4; r++) o[nt][r] = 0.f;

    for (int kt = 0; kt < ntiles; kt++) {
        const int n0 = kt * 64;

        // K: direct copy
        for (int t = tid; t < 512; t += 256) {
            int r = t >> 3, c8 = (t & 7) << 3;
            *(uint4*)&Ks[r * KS16 + c8] = *(const uint4*)(Kb + (size_t)(n0 + r) * PHD + c8);
        }
        // V: seq-pair interleave Vp[p][d] = (V[2p][d], V[2p+1][d])
        for (int t = tid; t < 512; t += 256) {
            int p = t >> 4, c4 = (t & 15) << 2;
            const __half2* a = (const __half2*)(Vb + (size_t)(n0 + 2 * p) * PHD + c4);
            const __half2* b = (const __half2*)(Vb + (size_t)(n0 + 2 * p + 1) * PHD + c4);
            __half2 a0 = a[0], a1 = a[1], b0 = b[0], b1 = b[1];
            __half2* d = &Vp[p * VP2 + c4];
            d[0] = __lows2half2(a0, b0);
            d[1] = __highs2half2(a0, b0);
            d[2] = __lows2half2(a1, b1);
            d[3] = __highs2half2(a1, b1);
        }
        __syncthreads();

        // S = Q K^T
        float s[8][4];
#pragma unroll
        for (int nt = 0; nt < 8; nt++)
#pragma unroll
            for (int r = 0; r < 4; r++) s[nt][r] = 0.f;

#pragma unroll
        for (int ks = 0; ks < 4; ks++) {
            const int kh = ks * 16 + 2 * cc;
#pragma unroll
            for (int nt = 0; nt < 8; nt++) {
                uint32_t b[2];
                memcpy(&b[0], &Ks[(nt * 8 + gr) * KS16 + kh], 4);
                memcpy(&b[1], &Ks[(nt * 8 + gr) * KS16 + kh + 8], 4);
                mma_f16(s[nt], qa[ks], b);
            }
        }

        // scale logits (fp32) then causal mask
#pragma unroll
        for (int nt = 0; nt < 8; nt++)
#pragma unroll
            for (int r = 0; r < 4; r++) s[nt][r] *= 0.125f;

        const int rlo = m0 + wr0 + gr;
        const int rhi = rlo + 8;
        if (causal && (n0 + 63 > rlo)) {
#pragma unroll
            for (int nt = 0; nt < 8; nt++) {
                const int c0 = n0 + nt * 8 + 2 * cc;
                if (c0 > rlo)     s[nt][0] = -1e30f;
                if (c0 + 1 > rlo) s[nt][1] = -1e30f;
                if (c0 > rhi)     s[nt][2] = -1e30f;
                if (c0 + 1 > rhi) s[nt][3] = -1e30f;
            }
        }

        // online softmax (warp-local)
        float tl = -1e30f, th = -1e30f;
#pragma unroll
        for (int nt = 0; nt < 8; nt++) {
            tl = fmaxf(tl, fmaxf(s[nt][0], s[nt][1]));
            th = fmaxf(th, fmaxf(s[nt][2], s[nt][3]));
        }
        tl = fmaxf(tl, __shfl_xor_sync(0xffffffffu, tl, 1));
        tl = fmaxf(tl, __shfl_xor_sync(0xffffffffu, tl, 2));
        th = fmaxf(th, __shfl_xor_sync(0xffffffffu, th, 1));
        th = fmaxf(th, __shfl_xor_sync(0xffffffffu, th, 2));

        const float mn0 = fmaxf(mr0, tl);
        const float mn1 = fmaxf(mr1, th);
        const float al0 = __expf(mr0 - mn0);
        const float al1 = __expf(mr1 - mn1);

        float sl = 0.f, sh = 0.f;
#pragma unroll
        for (int nt = 0; nt < 8; nt++) {
            float p0 = __expf(s[nt][0] - mn0);
            float p1 = __expf(s[nt][1] - mn0);
            float p2 = __expf(s[nt][2] - mn1);
            float p3 = __expf(s[nt][3] - mn1);
            sl += p0 + p1; sh += p2 + p3;
            uint32_t w0 = h2pack(p0, p1);
            uint32_t w1 = h2pack(p2, p3);
            memcpy(&Ps[(wr0 + gr) * PS16 + nt * 8 + 2 * cc], &w0, 4);
            memcpy(&Ps[(wr0 + gr + 8) * PS16 + nt * 8 + 2 * cc], &w1, 4);
        }
        sl += __shfl_xor_sync(0xffffffffu, sl, 1);
        sl += __shfl_xor_sync(0xffffffffu, sl, 2);
        sh += __shfl_xor_sync(0xffffffffu, sh, 1);
        sh += __shfl_xor_sync(0xffffffffu, sh, 2);

        lr0 = lr0 * al0 + sl;
        lr1 = lr1 * al1 + sh;
        mr0 = mn0; mr1 = mn1;

#pragma unroll
        for (int nt = 0; nt < 8; nt++) {
            o[nt][0] *= al0; o[nt][1] *= al0;
            o[nt][2] *= al1; o[nt][3] *= al1;
        }
        __syncwarp();

        // O += P V
#pragma unroll
        for (int ks = 0; ks < 4; ks++) {
            const int kh = ks * 16 + 2 * cc;
            const int pp = ks * 8 + cc;
            uint32_t a[4];
            memcpy(&a[0], &Ps[(wr0 + gr) * PS16 + kh], 4);
            memcpy(&a[1], &Ps[(wr0 + gr + 8) * PS16 + kh], 4);
            memcpy(&a[2], &Ps[(wr0 + gr) * PS16 + kh + 8], 4);
            memcpy(&a[3], &Ps[(wr0 + gr + 8) * PS16 + kh + 8], 4);
#pragma unroll
            for (int nt = 0; nt < 8; nt++) {
                uint32_t b[2];
                memcpy(&b[0], &Vp[pp * VP2 + nt * 8 + gr], 4);
                memcpy(&b[1], &Vp[(pp + 4) * VP2 + nt * 8 + gr], 4);
                mma_f16(o[nt], a, b);
            }
        }
        __syncthreads();
    }

    // epilogue (fp16 out)
    const float i0 = 1.0f / lr0;
    const float i1 = 1.0f / lr1;
#pragma unroll
    for (int nt = 0; nt < 8; nt++) {
        const int cb = nt * 8 + 2 * cc;
        uint32_t w0 = h2pack(o[nt][0] * i0, o[nt][1] * i0);
        uint32_t w1 = h2pack(o[nt][2] * i1, o[nt][3] * i1);
        memcpy(Ob + (size_t)(wr0 + gr) * PHD + cb, &w0, 4);
        memcpy(Ob + (size_t)(wr0 + gr + 8) * PHD + cb, &w1, 4);
    }
}

// ---------------------------------------------------------------------------
// Launch
// ---------------------------------------------------------------------------
extern "C" void kernel_launch(void* const* d_in, const int* in_sizes, int n_in,
                              void* d_out, int out_size)
{
    const float* q  = (const float*)d_in[0];
    const float* k  = (const float*)d_in[1];
    const float* v  = (const float*)d_in[2];
    const float* wq = (const float*)d_in[3];
    const float* wk = (const float*)d_in[4];
    const float* wv = (const float*)d_in[5];
    const float* wo = (const float*)d_in[6];
    const int*   am = (const int*)d_in[7];
    float* out = (float*)d_out;

    __half *qh, *kh, *vh, *wqh, *wkh, *wvh, *woh, *qp, *kp, *vp, *ao;
    cudaGetSymbolAddress((void**)&qh,  g_qh);
    cudaGetSymbolAddress((void**)&kh,  g_kh);
    cudaGetSymbolAddress((void**)&vh,  g_vh);
    cudaGetSymbolAddress((void**)&wqh, g_wqh);
    cudaGetSymbolAddress((void**)&wkh, g_wkh);
    cudaGetSymbolAddress((void**)&wvh, g_wvh);
    cudaGetSymbolAddress((void**)&woh, g_woh);
    cudaGetSymbolAddress((void**)&qp,  g_qp);
    cudaGetSymbolAddress((void**)&kp,  g_kp);
    cudaGetSymbolAddress((void**)&vp,  g_vp);
    cudaGetSymbolAddress((void**)&ao,  g_ao);

    // 1) fp32 -> fp16 conversion of inputs + weights
    dim3 gCvt((PM * PE) / (256 * 8), 7);   // (2048, 7)
    cvt_f2h<<<gCvt, 256>>>(q, k, v, wq, wk, wv, wo, qh, kh, vh, wqh, wkh, wvh, woh);

    // 2) fused Q/K/V projections (fp16 in, fp16 out)
    dim3 gQKV(PE / 128, PM / 128, 3);
    gemm_h<<<gQKV, 256>>>(qh, wqh, qp,  kh, wkh, kp,  vh, wvh, vp, 1, PM, PE, PE);

    // 3) attention (fp16 in/out)
    dim3 gAttn(PS / 128, PBH);
    flash_h<<<gAttn, 256>>>(qp, kp, vp, ao, am);

    // 4) output projection (fp16 in, fp32 out)
    dim3 gO(PE / 128, PM / 128, 1);
    gemm_h<<<gO, 256>>>(ao, woh, out,  ao, woh, out,  ao, woh, out, 0, PM, PE, PE);
}

// round 17
// speedup vs baseline: 1.2353x; 1.0961x over previous
#include <cuda_runtime.h>
#include <cuda_fp16.h>
#include <math_constants.h>
#include <cstdint>
#include <cstring>

// Problem constants
#define PB 2
#define PS 2048
#define PE 1024
#define PH 16
#define PHD 64
#define PBH (PB * PH)        // 32
#define PM (PB * PS)         // 4096

// ---------------------------------------------------------------------------
// helpers (sm_100-safe: mma.sync + cp.async only)
// ---------------------------------------------------------------------------
__device__ __forceinline__ uint32_t h2pack(float x, float y) {
    __half2 h = __floats2half2_rn(x, y);
    uint32_t u;
    memcpy(&u, &h, 4);
    return u;
}
__device__ __forceinline__ void mma_f16(float c[4], const uint32_t a[4], const uint32_t b[2]) {
    asm("mma.sync.aligned.m16n8k16.row.col.f32.f16.f16.f32 "
        "{%0,%1,%2,%3}, {%4,%5,%6,%7}, {%8,%9}, {%0,%1,%2,%3};"
        : "+f"(c[0]), "+f"(c[1]), "+f"(c[2]), "+f"(c[3])
        : "r"(a[0]), "r"(a[1]), "r"(a[2]), "r"(a[3]), "r"(b[0]), "r"(b[1]));
}
__device__ __forceinline__ uint32_t smem_u32(const void* p) {
    uint32_t a;
    asm("{ .reg .u64 t; cvta.to.shared.u64 t, %1; cvt.u32.u64 %0, t; }" : "=r"(a) : "l"(p));
    return a;
}
__device__ __forceinline__ void cp16(uint32_t s, const void* g) {
    asm volatile("cp.async.cg.shared.global [%0], [%1], 16;" :: "r"(s), "l"(g) : "memory");
}
#define CP_COMMIT() asm volatile("cp.async.commit_group;" ::: "memory")
#define CP_WAIT1()  asm volatile("cp.async.wait_group 1;" ::: "memory")
#define CP_WAIT0()  asm volatile("cp.async.wait_group 0;" ::: "memory")

// ---------------------------------------------------------------------------
// Scratch (no cudaMalloc allowed)
// ---------------------------------------------------------------------------
__device__ __half g_qh[PM * PE];
__device__ __half g_kh[PM * PE];
__device__ __half g_vh[PM * PE];
__device__ __half g_wqh[PE * PE];
__device__ __half g_wkh[PE * PE];
__device__ __half g_wvh[PE * PE];
__device__ __half g_woh[PE * PE];
__device__ __half g_qp[PM * PE];
__device__ __half g_kp[PM * PE];
__device__ __half g_vp[PM * PE];
__device__ __half g_ao[PM * PE];

// ---------------------------------------------------------------------------
// One-shot fp32 -> fp16 conversion
// ---------------------------------------------------------------------------
__global__ void cvt_f2h(const float* q, const float* k, const float* v,
                        const float* wq, const float* wk, const float* wv, const float* wo,
                        __half* qh, __half* kh, __half* vh,
                        __half* wqh, __half* wkh, __half* wvh, __half* woh)
{
    const int z = blockIdx.y;
    const float* s; __half* d; int n;
    switch (z) {
        case 0: s = q;  d = qh;  n = PM * PE; break;
        case 1: s = k;  d = kh;  n = PM * PE; break;
        case 2: s = v;  d = vh;  n = PM * PE; break;
        case 3: s = wq; d = wqh; n = PE * PE; break;
        case 4: s = wk; d = wkh; n = PE * PE; break;
        case 5: s = wv; d = wvh; n = PE * PE; break;
        default: s = wo; d = woh; n = PE * PE; break;
    }
    const int i = (blockIdx.x * 256 + threadIdx.x) * 8;
    if (i < n) {
        float4 a = *(const float4*)(s + i);
        float4 b = *(const float4*)(s + i + 4);
        *(uint4*)(d + i) = make_uint4(h2pack(a.x, a.y), h2pack(a.z, a.w),
                                      h2pack(b.x, b.y), h2pack(b.z, b.w));
    }
}

// ---------------------------------------------------------------------------
// FP16 GEMM (EXACT R16 version — proven): cp.async staging, 2-deep pipeline.
// CTA 128x128, 8 warps (2x4), warp tile 64x32, K-tile 32, pitch 40 halves.
// ---------------------------------------------------------------------------
#define GP16 40
#define GBUF (128 * GP16)

__global__ __launch_bounds__(256, 2)
void gemm_h(const __half* __restrict__ A0, const __half* __restrict__ B0, void* C0,
            const __half* __restrict__ A1, const __half* __restrict__ B1, void* C1,
            const __half* __restrict__ A2, const __half* __restrict__ B2, void* C2,
            int outHalf, int M, int N, int K)
{
    __shared__ __half Sm[2][2 * GBUF];

    const __half* A = A0; const __half* B = B0; void* Cv = C0;
    if (blockIdx.z == 1) { A = A1; B = B1; Cv = C1; }
    else if (blockIdx.z == 2) { A = A2; B = B2; Cv = C2; }

    const int tid  = threadIdx.x;
    const int lane = tid & 31;
    const int warp = tid >> 5;
    const int wm   = warp >> 2;
    const int wn   = warp & 3;
    const int gr   = lane >> 2;
    const int cc   = lane & 3;

    const int bm = blockIdx.y * 128;
    const int bn = blockIdx.x * 128;

    const int lr = tid >> 1;
    const int lq = (tid & 1) * 16;

    const __half* Agp = A + (size_t)(bm + lr) * K + lq;
    const __half* Bgp = B + (size_t)(bn + lr) * K + lq;
    const uint32_t sbase = smem_u32(Sm);
    const uint32_t aoff = (uint32_t)(lr * GP16 + lq) * 2;

    float acc[4][4][4];
#pragma unroll
    for (int mt = 0; mt < 4; mt++)
#pragma unroll
        for (int nt = 0; nt < 4; nt++)
#pragma unroll
            for (int r = 0; r < 4; r++) acc[mt][nt][r] = 0.f;

    auto stage = [&](int buf, int ko) {
        const uint32_t ad = sbase + (uint32_t)buf * (4 * GBUF) + aoff;
        const uint32_t bd = ad + 2 * GBUF;
        cp16(ad,      Agp + ko);
        cp16(ad + 16, Agp + ko + 8);
        cp16(bd,      Bgp + ko);
        cp16(bd + 16, Bgp + ko + 8);
        CP_COMMIT();
    };

    const int NT = K / 32;
    stage(0, 0);
    stage(1, 32);

    for (int t = 0; t < NT; t++) {
        if (t == NT - 1) { CP_WAIT0(); } else { CP_WAIT1(); }
        __syncthreads();

        const int buf = t & 1;
        const __half* As = &Sm[buf][0];
        const __half* Bs = As + GBUF;
#pragma unroll
        for (int s = 0; s < 2; s++) {
            const int kh = s * 16 + 2 * cc;
            uint32_t afr[4][4], bfr[4][2];
#pragma unroll
            for (int mt = 0; mt < 4; mt++) {
                const int r0 = wm * 64 + mt * 16 + gr;
                memcpy(&afr[mt][0], &As[r0 * GP16 + kh], 4);
                memcpy(&afr[mt][1], &As[(r0 + 8) * GP16 + kh], 4);
                memcpy(&afr[mt][2], &As[r0 * GP16 + kh + 8], 4);
                memcpy(&afr[mt][3], &As[(r0 + 8) * GP16 + kh + 8], 4);
            }
#pragma unroll
            for (int nt = 0; nt < 4; nt++) {
                const int nr = wn * 32 + nt * 8 + gr;
                memcpy(&bfr[nt][0], &Bs[nr * GP16 + kh], 4);
                memcpy(&bfr[nt][1], &Bs[nr * GP16 + kh + 8], 4);
            }
#pragma unroll
            for (int mt = 0; mt < 4; mt++)
#pragma unroll
                for (int nt = 0; nt < 4; nt++)
                    mma_f16(acc[mt][nt], afr[mt], bfr[nt]);
        }

        if (t + 2 < NT) {
            __syncthreads();
            stage(buf, (t + 2) * 32);
        }
    }

    if (outHalf) {
        __half* C = (__half*)Cv;
#pragma unroll
        for (int mt = 0; mt < 4; mt++) {
            const int r0 = bm + wm * 64 + mt * 16 + gr;
#pragma unroll
            for (int nt = 0; nt < 4; nt++) {
                const int cb = bn + wn * 32 + nt * 8 + 2 * cc;
                uint32_t w0 = h2pack(acc[mt][nt][0], acc[mt][nt][1]);
                uint32_t w1 = h2pack(acc[mt][nt][2], acc[mt][nt][3]);
                memcpy(C + (size_t)r0 * N + cb, &w0, 4);
                memcpy(C + (size_t)(r0 + 8) * N + cb, &w1, 4);
            }
        }
    } else {
        float* C = (float*)Cv;
#pragma unroll
        for (int mt = 0; mt < 4; mt++) {
            const int r0 = bm + wm * 64 + mt * 16 + gr;
#pragma unroll
            for (int nt = 0; nt < 4; nt++) {
                const int cb = bn + wn * 32 + nt * 8 + 2 * cc;
                *(float2*)(C + (size_t)r0 * N + cb)       = make_float2(acc[mt][nt][0], acc[mt][nt][1]);
                *(float2*)(C + (size_t)(r0 + 8) * N + cb) = make_float2(acc[mt][nt][2], acc[mt][nt][3]);
            }
        }
    }
}

// ---------------------------------------------------------------------------
// Flash attention v2, fp16 (fp32 softmax/accum).
// R16 structure + pipelined staging:
//   - K tiles via cp.async into double-buffered Ks (pure copy)
//   - V tiles LDG-prefetched into regs during compute, STS-interleaved after
//   - one __syncthreads per tile
//   - causal: heavy CTAs (large bx) launch first (bx reversed)
// smem (dynamic, 55296 B): Ks[2][64*72], Vp[2][32*72 half2], Ps[128*72]
// ---------------------------------------------------------------------------
#define KS16 72
#define PS16 72
#define VP2  72
#define FLASH_SMEM ((2 * 64 * KS16 + 128 * PS16) * 2 + 2 * 32 * VP2 * 4)

__global__ __launch_bounds__(256, 2)
void flash_h(const __half* __restrict__ Q, const __half* __restrict__ K,
             const __half* __restrict__ V, __half* __restrict__ O,
             const int* __restrict__ maskflag)
{
    extern __shared__ __half sm[];
    __half*  KsB = sm;                                   // [2][64*72]
    __half2* VpB = (__half2*)(sm + 2 * 64 * KS16);       // [2][32*72]
    __half*  Ps  = (__half*)(VpB + 2 * 32 * VP2);        // [128*72]

    const int tid  = threadIdx.x;
    const int lane = tid & 31;
    const int warp = tid >> 5;
    const int gr   = lane >> 2;
    const int cc   = lane & 3;
    const int bh   = blockIdx.y;
    const int bx   = (PS / 128 - 1) - blockIdx.x;   // heavy CTAs first
    const int m0   = bx * 128;
    const int wr0  = warp * 16;

    const __half* Qb = Q + (size_t)bh * PS * PHD;
    const __half* Kb = K + (size_t)bh * PS * PHD;
    const __half* Vb = V + (size_t)bh * PS * PHD;
    __half*       Ob = O + (size_t)bh * PS * PHD + (size_t)m0 * PHD;

    const uint32_t ksAddr = smem_u32(KsB);

    // K stage via cp.async: 512 x 16B per tile, 2 per thread
    const int kr0 = tid >> 3, kc0 = (tid & 7) << 3;            // e = tid
    const int kr1 = (tid + 256) >> 3, kc1 = ((tid + 256) & 7) << 3;
    auto stageK = [&](int buf, int n0) {
        const uint32_t base = ksAddr + (uint32_t)buf * (64 * KS16 * 2);
        cp16(base + (kr0 * KS16 + kc0) * 2, Kb + (size_t)(n0 + kr0) * PHD + kc0);
        cp16(base + (kr1 * KS16 + kc1) * 2, Kb + (size_t)(n0 + kr1) * PHD + kc1);
        CP_COMMIT();
    };

    // V prefetch (regs) + interleaved store
    const int vp0 = tid >> 4,         vc0 = (tid & 15) << 2;
    const int vp1 = (tid + 256) >> 4, vc1 = ((tid + 256) & 15) << 2;
    __half2 vr[2][4];
    auto prefV = [&](int n0) {
        const __half2* a0 = (const __half2*)(Vb + (size_t)(n0 + 2 * vp0) * PHD + vc0);
        const __half2* b0 = (const __half2*)(Vb + (size_t)(n0 + 2 * vp0 + 1) * PHD + vc0);
        vr[0][0] = a0[0]; vr[0][1] = a0[1]; vr[0][2] = b0[0]; vr[0][3] = b0[1];
        const __half2* a1 = (const __half2*)(Vb + (size_t)(n0 + 2 * vp1) * PHD + vc1);
        const __half2* b1 = (const __half2*)(Vb + (size_t)(n0 + 2 * vp1 + 1) * PHD + vc1);
        vr[1][0] = a1[0]; vr[1][1] = a1[1]; vr[1][2] = b1[0]; vr[1][3] = b1[1];
    };
    auto storeV = [&](int buf) {
        __half2* d0 = &VpB[buf * 32 * VP2 + vp0 * VP2 + vc0];
        d0[0] = __lows2half2(vr[0][0], vr[0][2]);
        d0[1] = __highs2half2(vr[0][0], vr[0][2]);
        d0[2] = __lows2half2(vr[0][1], vr[0][3]);
        d0[3] = __highs2half2(vr[0][1], vr[0][3]);
        __half2* d1 = &VpB[buf * 32 * VP2 + vp1 * VP2 + vc1];
        d1[0] = __lows2half2(vr[1][0], vr[1][2]);
        d1[1] = __highs2half2(vr[1][0], vr[1][2]);
        d1[2] = __lows2half2(vr[1][1], vr[1][3]);
        d1[3] = __highs2half2(vr[1][1], vr[1][3]);
    };

    // stage Q into Ps, extract persistent fragments
    for (int t = tid; t < 1024; t += 256) {
        int r = t >> 3, c8 = (t & 7) << 3;
        *(uint4*)&Ps[r * PS16 + c8] = *(const uint4*)(Qb + (size_t)(m0 + r) * PHD + c8);
    }
    stageK(0, 0);      // overlap with Q fragment extraction
    prefV(0);
    __syncthreads();

    uint32_t qa[4][4];
#pragma unroll
    for (int s = 0; s < 4; s++) {
        const int kh = s * 16 + 2 * cc;
        memcpy(&qa[s][0], &Ps[(wr0 + gr) * PS16 + kh], 4);
        memcpy(&qa[s][1], &Ps[(wr0 + gr + 8) * PS16 + kh], 4);
        memcpy(&qa[s][2], &Ps[(wr0 + gr) * PS16 + kh + 8], 4);
        memcpy(&qa[s][3], &Ps[(wr0 + gr + 8) * PS16 + kh + 8], 4);
    }
    storeV(0);
    CP_WAIT0();
    __syncthreads();   // K/V tile 0 ready; Q fragments extracted everywhere

    const bool causal = (*maskflag != 0);
    const int ntiles = causal ? (2 * bx + 2) : (PS / 64);

    float mr0 = -1e30f, mr1 = -1e30f, lr0 = 0.f, lr1 = 0.f;
    float o[8][4];
#pragma unroll
    for (int nt = 0; nt < 8; nt++)
#pragma unroll
        for (int r = 0; r < 4; r++) o[nt][r] = 0.f;

    for (int kt = 0; kt < ntiles; kt++) {
        const int n0 = kt * 64;
        const int buf = kt & 1;
        const bool more = (kt + 1 < ntiles);

        // issue next tile's staging before compute
        if (more) {
            stageK(buf ^ 1, n0 + 64);
            prefV(n0 + 64);
        }

        const __half*  Ks = KsB + buf * (64 * KS16);
        const __half2* Vp = VpB + buf * (32 * VP2);

        // S = Q K^T
        float s[8][4];
#pragma unroll
        for (int nt = 0; nt < 8; nt++)
#pragma unroll
            for (int r = 0; r < 4; r++) s[nt][r] = 0.f;

#pragma unroll
        for (int ks = 0; ks < 4; ks++) {
            const int kh = ks * 16 + 2 * cc;
#pragma unroll
            for (int nt = 0; nt < 8; nt++) {
                uint32_t b[2];
                memcpy(&b[0], &Ks[(nt * 8 + gr) * KS16 + kh], 4);
                memcpy(&b[1], &Ks[(nt * 8 + gr) * KS16 + kh + 8], 4);
                mma_f16(s[nt], qa[ks], b);
            }
        }

        // scale + causal mask
#pragma unroll
        for (int nt = 0; nt < 8; nt++)
#pragma unroll
            for (int r = 0; r < 4; r++) s[nt][r] *= 0.125f;

        const int rlo = m0 + wr0 + gr;
        const int rhi = rlo + 8;
        if (causal && (n0 + 63 > rlo)) {
#pragma unroll
            for (int nt = 0; nt < 8; nt++) {
                const int c0 = n0 + nt * 8 + 2 * cc;
                if (c0 > rlo)     s[nt][0] = -1e30f;
                if (c0 + 1 > rlo) s[nt][1] = -1e30f;
                if (c0 > rhi)     s[nt][2] = -1e30f;
                if (c0 + 1 > rhi) s[nt][3] = -1e30f;
            }
        }

        // online softmax (warp-local)
        float tl = -1e30f, th = -1e30f;
#pragma unroll
        for (int nt = 0; nt < 8; nt++) {
            tl = fmaxf(tl, fmaxf(s[nt][0], s[nt][1]));
            th = fmaxf(th, fmaxf(s[nt][2], s[nt][3]));
        }
        tl = fmaxf(tl, __shfl_xor_sync(0xffffffffu, tl, 1));
        tl = fmaxf(tl, __shfl_xor_sync(0xffffffffu, tl, 2));
        th = fmaxf(th, __shfl_xor_sync(0xffffffffu, th, 1));
        th = fmaxf(th, __shfl_xor_sync(0xffffffffu, th, 2));

        const float mn0 = fmaxf(mr0, tl);
        const float mn1 = fmaxf(mr1, th);
        const float al0 = __expf(mr0 - mn0);
        const float al1 = __expf(mr1 - mn1);

        float sl = 0.f, sh = 0.f;
#pragma unroll
        for (int nt = 0; nt < 8; nt++) {
            float p0 = __expf(s[nt][0] - mn0);
            float p1 = __expf(s[nt][1] - mn0);
            float p2 = __expf(s[nt][2] - mn1);
            float p3 = __expf(s[nt][3] - mn1);
            sl += p0 + p1; sh += p2 + p3;
            uint32_t w0 = h2pack(p0, p1);
            uint32_t w1 = h2pack(p2, p3);
            memcpy(&Ps[(wr0 + gr) * PS16 + nt * 8 + 2 * cc], &w0, 4);
            memcpy(&Ps[(wr0 + gr + 8) * PS16 + nt * 8 + 2 * cc], &w1, 4);
        }
        sl += __shfl_xor_sync(0xffffffffu, sl, 1);
        sl += __shfl_xor_sync(0xffffffffu, sl, 2);
        sh += __shfl_xor_sync(0xffffffffu, sh, 1);
        sh += __shfl_xor_sync(0xffffffffu, sh, 2);

        lr0 = lr0 * al0 + sl;
        lr1 = lr1 * al1 + sh;
        mr0 = mn0; mr1 = mn1;

#pragma unroll
        for (int nt = 0; nt < 8; nt++) {
            o[nt][0] *= al0; o[nt][1] *= al0;
            o[nt][2] *= al1; o[nt][3] *= al1;
        }
        __syncwarp();

        // O += P V
#pragma unroll
        for (int ks = 0; ks < 4; ks++) {
            const int kh = ks * 16 + 2 * cc;
            const int pp = ks * 8 + cc;
            uint32_t a[4];
            memcpy(&a[0], &Ps[(wr0 + gr) * PS16 + kh], 4);
            memcpy(&a[1], &Ps[(wr0 + gr + 8) * PS16 + kh], 4);
            memcpy(&a[2], &Ps[(wr0 + gr) * PS16 + kh + 8], 4);
            memcpy(&a[3], &Ps[(wr0 + gr + 8) * PS16 + kh + 8], 4);
#pragma unroll
            for (int nt = 0; nt < 8; nt++) {
                uint32_t b[2];
                memcpy(&b[0], &Vp[pp * VP2 + nt * 8 + gr], 4);
                memcpy(&b[1], &Vp[(pp + 4) * VP2 + nt * 8 + gr], 4);
                mma_f16(o[nt], a, b);
            }
        }

        // finish next tile's staging, then single barrier
        if (more) {
            storeV(buf ^ 1);
            CP_WAIT0();
        }
        __syncthreads();
    }

    // epilogue (fp16 out)
    const float i0 = 1.0f / lr0;
    const float i1 = 1.0f / lr1;
#pragma unroll
    for (int nt = 0; nt < 8; nt++) {
        const int cb = nt * 8 + 2 * cc;
        uint32_t w0 = h2pack(o[nt][0] * i0, o[nt][1] * i0);
        uint32_t w1 = h2pack(o[nt][2] * i1, o[nt][3] * i1);
        memcpy(Ob + (size_t)(wr0 + gr) * PHD + cb, &w0, 4);
        memcpy(Ob + (size_t)(wr0 + gr + 8) * PHD + cb, &w1, 4);
    }
}

// ---------------------------------------------------------------------------
// Launch
// ---------------------------------------------------------------------------
extern "C" void kernel_launch(void* const* d_in, const int* in_sizes, int n_in,
                              void* d_out, int out_size)
{
    const float* q  = (const float*)d_in[0];
    const float* k  = (const float*)d_in[1];
    const float* v  = (const float*)d_in[2];
    const float* wq = (const float*)d_in[3];
    const float* wk = (const float*)d_in[4];
    const float* wv = (const float*)d_in[5];
    const float* wo = (const float*)d_in[6];
    const int*   am = (const int*)d_in[7];
    float* out = (float*)d_out;

    __half *qh, *kh, *vh, *wqh, *wkh, *wvh, *woh, *qp, *kp, *vp, *ao;
    cudaGetSymbolAddress((void**)&qh,  g_qh);
    cudaGetSymbolAddress((void**)&kh,  g_kh);
    cudaGetSymbolAddress((void**)&vh,  g_vh);
    cudaGetSymbolAddress((void**)&wqh, g_wqh);
    cudaGetSymbolAddress((void**)&wkh, g_wkh);
    cudaGetSymbolAddress((void**)&wvh, g_wvh);
    cudaGetSymbolAddress((void**)&woh, g_woh);
    cudaGetSymbolAddress((void**)&qp,  g_qp);
    cudaGetSymbolAddress((void**)&kp,  g_kp);
    cudaGetSymbolAddress((void**)&vp,  g_vp);
    cudaGetSymbolAddress((void**)&ao,  g_ao);

    cudaFuncSetAttribute(flash_h, cudaFuncAttributeMaxDynamicSharedMemorySize, FLASH_SMEM);

    // 1) fp32 -> fp16 conversion
    dim3 gCvt((PM * PE) / (256 * 8), 7);
    cvt_f2h<<<gCvt, 256>>>(q, k, v, wq, wk, wv, wo, qh, kh, vh, wqh, wkh, wvh, woh);

    // 2) fused Q/K/V projections (fp16 in/out)
    dim3 gQKV(PE / 128, PM / 128, 3);
    gemm_h<<<gQKV, 256>>>(qh, wqh, qp,  kh, wkh, kp,  vh, wvh, vp, 1, PM, PE, PE);

    // 3) attention (fp16 in/out)
    dim3 gAttn(PS / 128, PBH);
    flash_h<<<gAttn, 256, FLASH_SMEM>>>(qp, kp, vp, ao, am);

    // 4) output projection (fp16 in, fp32 out)
    dim3 gO(PE / 128, PM / 128, 1);
    gemm_h<<<gO, 256>>>(ao, woh, out,  ao, woh, out,  ao, woh, out, 0, PM, PE, PE);
}